// round 17
// baseline (speedup 1.0000x reference)
#include <cuda_runtime.h>
#include <cuda_bf16.h>
#include <cstdint>

#define Bq 1024
#define Lq 100
#define NBLK 256
#define NTHR 256

typedef unsigned long long u64;
typedef __nv_bfloat16 bf16;

// ---------------- static scratch ----------------
__device__ __align__(16) unsigned char g_W0sw[16 * 12 * 16384];  // 3 MB
__device__ __align__(16) unsigned char g_W1sw[16 * 8 * 16384];   // 2 MB
__device__ __align__(16) unsigned char g_Waw[4 * 4 * 16384];
__device__ __align__(16) unsigned char g_Wccw[4 * 8 * 16384];
__device__ __align__(16) unsigned char g_Wskw[8 * 4 * 16384];
__device__ float g_Wco[256 * 256];
__device__ float g_b0p[1024], g_b1p[1024];
// bf16 hi/lo activation images
__device__ __align__(16) bf16 g_embh[256 * 256], g_embl[256 * 256];
__device__ __align__(16) bf16 g_ctxh[Bq * 256], g_ctxl[Bq * 256];
__device__ __align__(16) bf16 g_h0ah[Bq * 256], g_h0al[Bq * 256];
__device__ __align__(16) bf16 g_h0bh[Bq * 256], g_h0bl[Bq * 256];
__device__ __align__(16) bf16 g_h1ah[Bq * 256], g_h1al[Bq * 256];
__device__ __align__(16) bf16 g_h1bh[Bq * 256], g_h1bl[Bq * 256];
__device__ __align__(16) bf16 g_cah[Bq * 256], g_cal[Bq * 256];
__device__ float g_c0[Bq * 256], g_c1[Bq * 256];
__device__ float g_q[Bq * 256], g_pre[Bq * 256];
__device__ float g_logit[Bq * 256], g_Q[Bq * 256];
__device__ unsigned g_count;

// ---------------- smem layout (per block): M=64 tiles ----------------
// A bufs: [0, 32768): per buf hi 8KB + lo 8KB. W bufs: [32768, 65536).
#define AHI_OFF(b) ((b) * 16384)
#define ALO_OFF(b) (AHI_OFF(b) + 8192)
#define WHI_OFF(b) (32768 + (b) * 16384)
#define WLO_OFF(b) (WHI_OFF(b) + 8192)
#define SMEM_TOTAL 66560

#define SWZ(x) ((x) ^ (((x) >> 3) & 0x70))

__device__ __forceinline__ float sigm(float x) { return 1.f / (1.f + __expf(-x)); }

// ---------------- primitives ----------------
__device__ __forceinline__ uint32_t smem_u32(const void* p) {
    uint32_t a;
    asm("{ .reg .u64 t; cvta.to.shared.u64 t, %1; cvt.u32.u64 %0, t; }"
        : "=r"(a) : "l"(p));
    return a;
}
__device__ __forceinline__ void ldg_el8(const float* p, float4& a, float4& b) {
    uint32_t r0, r1, r2, r3, r4, r5, r6, r7;
    asm volatile("ld.global.nc.L2::evict_last.v8.b32 "
                 "{%0,%1,%2,%3,%4,%5,%6,%7}, [%8];"
                 : "=r"(r0), "=r"(r1), "=r"(r2), "=r"(r3),
                   "=r"(r4), "=r"(r5), "=r"(r6), "=r"(r7) : "l"(p));
    a.x = __uint_as_float(r0); a.y = __uint_as_float(r1);
    a.z = __uint_as_float(r2); a.w = __uint_as_float(r3);
    b.x = __uint_as_float(r4); b.y = __uint_as_float(r5);
    b.z = __uint_as_float(r6); b.w = __uint_as_float(r7);
}
#define LDSM4(r, a) asm volatile( \
    "ldmatrix.sync.aligned.m8n8.x4.shared.b16 {%0,%1,%2,%3}, [%4];" \
    : "=r"((r)[0]), "=r"((r)[1]), "=r"((r)[2]), "=r"((r)[3]) : "r"(a))
#define LDSM4T(r, a) asm volatile( \
    "ldmatrix.sync.aligned.m8n8.x4.trans.shared.b16 {%0,%1,%2,%3}, [%4];" \
    : "=r"((r)[0]), "=r"((r)[1]), "=r"((r)[2]), "=r"((r)[3]) : "r"(a))
__device__ __forceinline__ void mma16816(float* d, const uint32_t* a,
                                         uint32_t b0, uint32_t b1) {
    asm volatile("mma.sync.aligned.m16n8k16.row.col.f32.bf16.bf16.f32 "
                 "{%0,%1,%2,%3}, {%4,%5,%6,%7}, {%8,%9}, {%0,%1,%2,%3};"
                 : "+f"(d[0]), "+f"(d[1]), "+f"(d[2]), "+f"(d[3])
                 : "r"(a[0]), "r"(a[1]), "r"(a[2]), "r"(a[3]), "r"(b0), "r"(b1));
}
__device__ __forceinline__ uint32_t pkbf(float a, float b) {
    uint16_t ua = __bfloat16_as_ushort(__float2bfloat16(a));
    uint16_t ub = __bfloat16_as_ushort(__float2bfloat16(b));
    return (uint32_t)ua | ((uint32_t)ub << 16);
}
__device__ __forceinline__ void split2(float a, float b, uint32_t& h, uint32_t& l) {
    bf16 ha = __float2bfloat16(a), hb = __float2bfloat16(b);
    h = (uint32_t)__bfloat16_as_ushort(ha) | ((uint32_t)__bfloat16_as_ushort(hb) << 16);
    l = pkbf(a - __bfloat162float(ha), b - __bfloat162float(hb));
}
__device__ __forceinline__ void split1(float a, bf16* ph, bf16* pl) {
    bf16 h = __float2bfloat16(a);
    *ph = h;
    *pl = __float2bfloat16(a - __bfloat162float(h));
}

// ---------------- grid barrier ----------------
__device__ __forceinline__ void gsync(unsigned target) {
    __syncthreads();
    if (threadIdx.x == 0) {
        asm volatile("red.add.release.gpu.u32 [%0], 1;"
                     :: "l"(&g_count) : "memory");
        unsigned cur;
        do {
            asm volatile("ld.acquire.gpu.u32 %0, [%1];"
                         : "=r"(cur) : "l"(&g_count) : "memory");
        } while ((int)(cur - target) < 0);
    }
    __syncthreads();
}

// ---------------- tail pool (overlay on dynsm) ----------------
struct TailPool {
    struct { float acc[4][256]; float m1[4], e1[4]; } att;
};

// =============== shared A/W staging (M=64 tile, 256 threads) =================
// A: row = tid>>2 (64 rows), kg = tid&3 -> cols kg*16..+15 (2x uint4 hi + lo)
// W: flat copy 32B hi + 32B lo per thread
struct Pref {
    uint4 ah0, ah1, al0, al1, wh0, wh1, wl0, wl1;
};
__device__ __forceinline__ void stage(char* sm, int buf, int row, int kg,
                                      const Pref& p) {
    uint32_t b0 = row * 128 + kg * 32;
    uint32_t s0 = SWZ(b0), s1 = SWZ(b0 + 16);
    *(uint4*)(sm + AHI_OFF(buf) + s0) = p.ah0;
    *(uint4*)(sm + AHI_OFF(buf) + s1) = p.ah1;
    *(uint4*)(sm + ALO_OFF(buf) + s0) = p.al0;
    *(uint4*)(sm + ALO_OFF(buf) + s1) = p.al1;
    const int tid = threadIdx.x;
    *(uint4*)(sm + WHI_OFF(buf) + tid * 32) = p.wh0;
    *(uint4*)(sm + WHI_OFF(buf) + tid * 32 + 16) = p.wh1;
    *(uint4*)(sm + WLO_OFF(buf) + tid * 32) = p.wl0;
    *(uint4*)(sm + WLO_OFF(buf) + tid * 32 + 16) = p.wl1;
}
__device__ __forceinline__ void pref_W(Pref& p, const unsigned char* Wsw, int cn) {
    const int tid = threadIdx.x;
    const unsigned char* base = Wsw + (size_t)cn * 16384;
    p.wh0 = __ldcs((const uint4*)(base + tid * 32));
    p.wh1 = __ldcs((const uint4*)(base + tid * 32 + 16));
    p.wl0 = __ldcs((const uint4*)(base + 8192 + tid * 32));
    p.wl1 = __ldcs((const uint4*)(base + 8192 + tid * 32 + 16));
}
__device__ __forceinline__ void pref_A(Pref& p, const bf16* Ah, const bf16* Al,
                                       int ri, int kc) {
    const uint4* ph = (const uint4*)(Ah + (size_t)ri * 256 + kc);
    const uint4* pl = (const uint4*)(Al + (size_t)ri * 256 + kc);
    p.ah0 = ph[0]; p.ah1 = ph[1];
    p.al0 = pl[0]; p.al1 = pl[1];
}

// =============== core mma loop (shared by LSTM and out GEMMs) ================
// d[4][4]: nt 0..3 (cols nw*32 + nt*8), rows mw*16..+15
__device__ __forceinline__ void mma_chunk(uint32_t smb, int buf, int lrowA,
                                          int lksel, int lrowB, int ljB,
                                          float d[4][4]) {
    const uint32_t ah_base = smb + AHI_OFF(buf);
    const uint32_t al_base = smb + ALO_OFF(buf);
    const uint32_t wh_base = smb + WHI_OFF(buf);
    const uint32_t wl_base = smb + WLO_OFF(buf);
#pragma unroll
    for (int ks = 0; ks < 4; ks++) {
        uint32_t ah[4], al[4], bh[8], bl[8];
        {
            uint32_t off = SWZ((uint32_t)(lrowA * 128 + (ks * 2 + lksel) * 16));
            LDSM4(ah, ah_base + off);
            LDSM4(al, al_base + off);
        }
        {
            uint32_t o1 = SWZ((uint32_t)((ks * 16 + lrowB) * 128 + ljB * 16));
            uint32_t o2 = SWZ((uint32_t)((ks * 16 + lrowB) * 128 + (ljB + 2) * 16));
            LDSM4T(bh, wh_base + o1);
            LDSM4T(bh + 4, wh_base + o2);
            LDSM4T(bl, wl_base + o1);
            LDSM4T(bl + 4, wl_base + o2);
        }
#pragma unroll
        for (int nt = 0; nt < 4; nt++) {
            mma16816(d[nt], ah, bh[2 * nt], bh[2 * nt + 1]);
            mma16816(d[nt], ah, bl[2 * nt], bl[2 * nt + 1]);
            mma16816(d[nt], al, bh[2 * nt], bh[2 * nt + 1]);
        }
    }
}

// =============== LSTM: M=64 x N=64 gate tile, cell epilogue ==================
__device__ void lstm_mma(char* sm, uint32_t smb, const int* gidx, int bm, int ct,
                         const bf16* A0h, const bf16* A0l,
                         const bf16* A1h, const bf16* A1l,
                         const bf16* A2h, const bf16* A2l,
                         int nch, bool gather,
                         const unsigned char* __restrict__ Wsw,
                         const float* __restrict__ bias,
                         float* __restrict__ cst,
                         bf16* __restrict__ houth, bf16* __restrict__ houtl) {
    const int tid = threadIdx.x;
    const int warp = tid >> 5, lane = tid & 31;
    const int mw = warp & 3, nw = warp >> 2;
    const int row = tid >> 2, kg = tid & 3;

    float d[4][4];
#pragma unroll
    for (int nt = 0; nt < 4; nt++)
#pragma unroll
        for (int e = 0; e < 4; e++) d[nt][e] = 0.f;

    const int lrowA = mw * 16 + (lane & 15);
    const int lksel = lane >> 4;
    const int lrowB = lane & 15;
    const int ljB = nw * 4 + (lane >> 4);

    Pref p;
    {
        int ri = gather ? gidx[row] : (bm + row);
        pref_A(p, A0h, A0l, ri, kg * 16);
        pref_W(p, Wsw, 0);
    }
    for (int c = 0; c < nch; c++) {
        const int buf = c & 1;
        stage(sm, buf, row, kg, p);
        __syncthreads();
        if (c + 1 < nch) {
            int cn = c + 1;
            int seg = cn >> 2;
            int kc = ((cn & 3) * 64) + kg * 16;
            const bf16* Ah = (seg == 0) ? A0h : (seg == 1 ? A1h : A2h);
            const bf16* Al = (seg == 0) ? A0l : (seg == 1 ? A1l : A2l);
            int ri = (gather && seg == 0) ? gidx[row] : (bm + row);
            pref_A(p, Ah, Al, ri, kc);
            pref_W(p, Wsw, cn);
        }
        mma_chunk(smb, buf, lrowA, lksel, lrowB, ljB, d);
    }
    // frag -> Dsm (64x64 f32, 16KB, buf0 A region; last chunk used buf1)
    {
        float* Dsm = (float*)sm;
        int r = mw * 16 + (lane >> 2);
#pragma unroll
        for (int nt = 0; nt < 4; nt++) {
            int cc = nw * 32 + nt * 8 + 2 * (lane & 3);
            *(float2*)(Dsm + r * 64 + cc) = make_float2(d[nt][0], d[nt][1]);
            *(float2*)(Dsm + (r + 8) * 64 + cc) = make_float2(d[nt][2], d[nt][3]);
        }
    }
    __syncthreads();
    // LSTM cell: 1024 cells, 4 per thread
    {
        const float* Dsm = (const float*)sm;
#pragma unroll
        for (int i = 0; i < 4; i++) {
            int e = tid + i * 256;
            int r = e >> 4, hl = e & 15;
            float4 g4 = *(const float4*)(Dsm + r * 64 + hl * 4);
            int nb = ct * 64 + hl * 4;
            float gi = g4.x + bias[nb + 0];
            float gf = g4.y + bias[nb + 1];
            float gg = g4.z + bias[nb + 2];
            float go = g4.w + bias[nb + 3];
            float I = sigm(gi), F = sigm(gf);
            float G = tanhf(gg), Og = sigm(go);
            int idx = (bm + r) * 256 + ct * 16 + hl;
            float cn = F * cst[idx] + I * G;
            cst[idx] = cn;
            split1(Og * tanhf(cn), houth + idx, houtl + idx);
        }
    }
    __syncthreads();
}

// =============== output GEMM: M=64 x N=64, modes 0/3/4 =======================
__device__ void mma_out64(char* sm, uint32_t smb, int bm, int ct,
                          const bf16* Ah, const bf16* Al, int nch,
                          const unsigned char* __restrict__ Wsw,
                          const float* __restrict__ bias, int mode,
                          float* __restrict__ C0, float* __restrict__ C1,
                          bf16* __restrict__ Ch, bf16* __restrict__ Cl) {
    const int tid = threadIdx.x;
    const int warp = tid >> 5, lane = tid & 31;
    const int mw = warp & 3, nw = warp >> 2;
    const int row = tid >> 2, kg = tid & 3;

    float d[4][4];
#pragma unroll
    for (int nt = 0; nt < 4; nt++)
#pragma unroll
        for (int e = 0; e < 4; e++) d[nt][e] = 0.f;

    const int lrowA = mw * 16 + (lane & 15);
    const int lksel = lane >> 4;
    const int lrowB = lane & 15;
    const int ljB = nw * 4 + (lane >> 4);

    Pref p;
    pref_A(p, Ah, Al, bm + row, kg * 16);
    pref_W(p, Wsw, 0);

    for (int c = 0; c < nch; c++) {
        const int buf = c & 1;
        stage(sm, buf, row, kg, p);
        __syncthreads();
        if (c + 1 < nch) {
            int cn = c + 1;
            pref_A(p, Ah, Al, bm + row, cn * 64 + kg * 16);
            pref_W(p, Wsw, cn);
        }
        mma_chunk(smb, buf, lrowA, lksel, lrowB, ljB, d);
    }
    const int r = bm + mw * 16 + (lane >> 2);
#pragma unroll
    for (int nt = 0; nt < 4; nt++) {
        int cc = nw * 32 + nt * 8 + 2 * (lane & 3);
        int colg = ct * 64 + cc;
        float2 v0 = make_float2(d[nt][0], d[nt][1]);
        float2 v1 = make_float2(d[nt][2], d[nt][3]);
        if (mode == 4) {
            float2 p0 = *(const float2*)(C1 + (size_t)r * 256 + colg);
            float2 p1 = *(const float2*)(C1 + (size_t)(r + 8) * 256 + colg);
            float t0 = tanhf(v0.x + p0.x), t1 = tanhf(v0.y + p0.y);
            float t2 = tanhf(v1.x + p1.x), t3 = tanhf(v1.y + p1.y);
            uint32_t h, l;
            split2(t0, t1, h, l);
            *(uint32_t*)(Ch + (size_t)r * 256 + colg) = h;
            *(uint32_t*)(Cl + (size_t)r * 256 + colg) = l;
            split2(t2, t3, h, l);
            *(uint32_t*)(Ch + (size_t)(r + 8) * 256 + colg) = h;
            *(uint32_t*)(Cl + (size_t)(r + 8) * 256 + colg) = l;
        } else if (mode == 3 && colg >= 256) {
            float b0 = bias[colg - 256], b1 = bias[colg - 255];
            v0.x += b0; v0.y += b1; v1.x += b0; v1.y += b1;
            *(float2*)(C1 + (size_t)r * 256 + colg - 256) = v0;
            *(float2*)(C1 + (size_t)(r + 8) * 256 + colg - 256) = v1;
        } else {
            *(float2*)(C0 + (size_t)r * 256 + colg) = v0;
            *(float2*)(C0 + (size_t)(r + 8) * 256 + colg) = v1;
        }
    }
    __syncthreads();
}

// =============== attention: 4 rows/block, 2 warps/row, online softmax ========
__device__ void attention4(TailPool* sp, int bid, const float* __restrict__ eo) {
    const int tid = threadIdx.x, w = tid >> 5, lane = tid & 31;
    const int r4 = w >> 1, half = w & 1, b = bid * 4 + r4;
    const float* qb = g_q + b * 256;
    float4 q0 = *(const float4*)(qb + lane * 8);
    float4 q1 = *(const float4*)(qb + lane * 8 + 4);
    const float* eb = eo + (size_t)b * Lq * 256;
    float m = -1e30f, esum = 0.f;
    float4 a0 = make_float4(0, 0, 0, 0), a1 = make_float4(0, 0, 0, 0);
    const int l0 = half * 50;
    float4 c00, c01, c10, c11;
    ldg_el8(eb + (size_t)l0 * 256 + lane * 8, c00, c01);
    ldg_el8(eb + (size_t)(l0 + 1) * 256 + lane * 8, c10, c11);
#pragma unroll 5
    for (int l = l0; l < l0 + 50; l += 2) {
        float4 n00, n01, n10, n11;
        if (l + 2 < l0 + 50) {
            ldg_el8(eb + (size_t)(l + 2) * 256 + lane * 8, n00, n01);
            ldg_el8(eb + (size_t)(l + 3) * 256 + lane * 8, n10, n11);
        }
#pragma unroll
        for (int jj = 0; jj < 2; jj++) {
            float4 v0 = jj ? c10 : c00;
            float4 v1 = jj ? c11 : c01;
            float s = v0.x * q0.x + v0.y * q0.y + v0.z * q0.z + v0.w * q0.w
                    + v1.x * q1.x + v1.y * q1.y + v1.z * q1.z + v1.w * q1.w;
#pragma unroll
            for (int o = 16; o; o >>= 1) s += __shfl_xor_sync(0xFFFFFFFFu, s, o);
            if (s <= m) {
                float wg = __expf(s - m);
                esum += wg;
                a0.x += wg * v0.x; a0.y += wg * v0.y; a0.z += wg * v0.z; a0.w += wg * v0.w;
                a1.x += wg * v1.x; a1.y += wg * v1.y; a1.z += wg * v1.z; a1.w += wg * v1.w;
            } else {
                float r = __expf(m - s);
                esum = esum * r + 1.f;
                a0.x = a0.x * r + v0.x; a0.y = a0.y * r + v0.y;
                a0.z = a0.z * r + v0.z; a0.w = a0.w * r + v0.w;
                a1.x = a1.x * r + v1.x; a1.y = a1.y * r + v1.y;
                a1.z = a1.z * r + v1.z; a1.w = a1.w * r + v1.w;
                m = s;
            }
        }
        c00 = n00; c01 = n01; c10 = n10; c11 = n11;
    }
    if (half) {
        sp->att.m1[r4] = m; sp->att.e1[r4] = esum;
        *(float4*)&sp->att.acc[r4][lane * 8] = a0;
        *(float4*)&sp->att.acc[r4][lane * 8 + 4] = a1;
    }
    __syncthreads();
    if (!half) {
        float m1 = sp->att.m1[r4], e1 = sp->att.e1[r4];
        float M = fmaxf(m, m1);
        float s0 = __expf(m - M), s1 = __expf(m1 - M);
        float inv = 1.f / (esum * s0 + e1 * s1);
        float4 p0 = *(const float4*)&sp->att.acc[r4][lane * 8];
        float4 p1 = *(const float4*)&sp->att.acc[r4][lane * 8 + 4];
        float o[8];
        o[0] = (a0.x * s0 + p0.x * s1) * inv; o[1] = (a0.y * s0 + p0.y * s1) * inv;
        o[2] = (a0.z * s0 + p0.z * s1) * inv; o[3] = (a0.w * s0 + p0.w * s1) * inv;
        o[4] = (a1.x * s0 + p1.x * s1) * inv; o[5] = (a1.y * s0 + p1.y * s1) * inv;
        o[6] = (a1.z * s0 + p1.z * s1) * inv; o[7] = (a1.w * s0 + p1.w * s1) * inv;
        uint32_t h0, l0p, h1, l1, h2, l2, h3, l3;
        split2(o[0], o[1], h0, l0p); split2(o[2], o[3], h1, l1);
        split2(o[4], o[5], h2, l2);  split2(o[6], o[7], h3, l3);
        *(uint4*)(g_cah + b * 256 + lane * 8) = make_uint4(h0, h1, h2, h3);
        *(uint4*)(g_cal + b * 256 + lane * 8) = make_uint4(l0p, l1, l2, l3);
    }
    __syncthreads();
}

// =============== finalize: warp-per-row, 4 rows/block ========================
__device__ void finalize4(int bid, int t, const int* __restrict__ actions,
                          float* __restrict__ out) {
    const int w = threadIdx.x >> 5, lane = threadIdx.x & 31;
    if (w >= 4) return;
    const int b = bid * 4 + w;
    const float* lr = g_logit + b * 256;
    float4 l0 = *(const float4*)(lr + lane * 4);
    float4 l1 = *(const float4*)(lr + 128 + lane * 4);
    float m = fmaxf(fmaxf(fmaxf(l0.x, l0.y), fmaxf(l0.z, l0.w)),
                    fmaxf(fmaxf(l1.x, l1.y), fmaxf(l1.z, l1.w)));
#pragma unroll
    for (int o = 16; o; o >>= 1) m = fmaxf(m, __shfl_xor_sync(0xFFFFFFFFu, m, o));
    float4 e0 = make_float4(__expf(l0.x - m), __expf(l0.y - m), __expf(l0.z - m), __expf(l0.w - m));
    float4 e1 = make_float4(__expf(l1.x - m), __expf(l1.y - m), __expf(l1.z - m), __expf(l1.w - m));
    float s = e0.x + e0.y + e0.z + e0.w + e1.x + e1.y + e1.z + e1.w;
#pragma unroll
    for (int o = 16; o; o >>= 1) s += __shfl_xor_sync(0xFFFFFFFFu, s, o);
    float inv = 1.f / s;
    e0.x *= inv; e0.y *= inv; e0.z *= inv; e0.w *= inv;
    e1.x *= inv; e1.y *= inv; e1.z *= inv; e1.w *= inv;
    float* outl = out + (size_t)Bq * Lq + ((size_t)b * Lq + t) * 256;
    *(float4*)(outl + lane * 4) = e0;
    *(float4*)(outl + 128 + lane * 4) = e1;
    const float* Qr = g_Q + b * 256;
    float4 Q0 = *(const float4*)(Qr + lane * 4);
    float4 Q1 = *(const float4*)(Qr + 128 + lane * 4);
    float v = e0.x * Q0.x + e0.y * Q0.y + e0.z * Q0.z + e0.w * Q0.w
            + e1.x * Q1.x + e1.y * Q1.y + e1.z * Q1.z + e1.w * Q1.w;
#pragma unroll
    for (int o = 16; o; o >>= 1) v += __shfl_xor_sync(0xFFFFFFFFu, v, o);
    if (!lane) {
        out[(size_t)Bq * Lq + (size_t)Bq * Lq * 256 + b * Lq + t] = v;
        out[b * Lq + t] = (float)actions[b * Lq + t];
    }
}

// =============== persistent mega-kernel ======================================
__global__ void __launch_bounds__(NTHR, 2)
mega(const float* __restrict__ enc_out, const float* __restrict__ enc_h,
     const float* __restrict__ enc_c, const float* __restrict__ emb,
     const float* __restrict__ Wih0, const float* __restrict__ Whh0,
     const float* __restrict__ bih0, const float* __restrict__ bhh0,
     const float* __restrict__ Wih1, const float* __restrict__ Whh1,
     const float* __restrict__ bih1, const float* __restrict__ bhh1,
     const float* __restrict__ Wa, const float* __restrict__ Wconcat,
     const float* __restrict__ Wout, const float* __restrict__ Wcrit,
     const float* __restrict__ bcrit, const int* __restrict__ actions,
     float* __restrict__ out) {
    extern __shared__ char dynsm[];
    TailPool* sp = (TailPool*)dynsm;
    __shared__ int gidx[64];
    const int bid = blockIdx.x, tid = threadIdx.x;
    const uint32_t smb = smem_u32(dynsm);
    unsigned bt = 0;

    // ---- init (total threads NBLK*NTHR = 65536, identical to R16) ----
    for (int idx = bid * NTHR + tid; idx < 16 * 12 * 4096; idx += NBLK * NTHR) {
        int ct = idx / 49152, rem = idx - ct * 49152;
        int ch = rem >> 12, rr = rem & 4095;
        int k = rr >> 6, n = rr & 63;
        int np = ct * 64 + n, h = np >> 2, g = np & 3, orow = g * 256 + h;
        int kk = ch * 64 + k;
        float w = (kk < 512) ? Wih0[orow * 512 + kk] : Whh0[orow * 256 + (kk - 512)];
        bf16 hi = __float2bfloat16(w);
        bf16 lo = __float2bfloat16(w - __bfloat162float(hi));
        unsigned char* base = g_W0sw + (size_t)(ct * 12 + ch) * 16384;
        uint32_t off = SWZ((uint32_t)(k * 128 + n * 2));
        *(bf16*)(base + off) = hi;
        *(bf16*)(base + 8192 + off) = lo;
    }
    for (int idx = bid * NTHR + tid; idx < 16 * 8 * 4096; idx += NBLK * NTHR) {
        int ct = idx / 32768, rem = idx - ct * 32768;
        int ch = rem >> 12, rr = rem & 4095;
        int k = rr >> 6, n = rr & 63;
        int np = ct * 64 + n, h = np >> 2, g = np & 3, orow = g * 256 + h;
        int kk = ch * 64 + k;
        float w = (kk < 256) ? Wih1[orow * 256 + kk] : Whh1[orow * 256 + (kk - 256)];
        bf16 hi = __float2bfloat16(w);
        bf16 lo = __float2bfloat16(w - __bfloat162float(hi));
        unsigned char* base = g_W1sw + (size_t)(ct * 8 + ch) * 16384;
        uint32_t off = SWZ((uint32_t)(k * 128 + n * 2));
        *(bf16*)(base + off) = hi;
        *(bf16*)(base + 8192 + off) = lo;
    }
    for (int idx = bid * NTHR + tid; idx < 4 * 4 * 4096; idx += NBLK * NTHR) {
        int ct = idx / 16384, rem = idx - ct * 16384;
        int ch = rem >> 12, rr = rem & 4095;
        int k = rr >> 6, n = rr & 63;
        int np = ct * 64 + n, kk = ch * 64 + k;
        float w = Wa[kk * 256 + np];
        bf16 hi = __float2bfloat16(w);
        bf16 lo = __float2bfloat16(w - __bfloat162float(hi));
        unsigned char* base = g_Waw + (size_t)(ct * 4 + ch) * 16384;
        uint32_t off = SWZ((uint32_t)(k * 128 + n * 2));
        *(bf16*)(base + off) = hi;
        *(bf16*)(base + 8192 + off) = lo;
    }
    for (int idx = bid * NTHR + tid; idx < 4 * 8 * 4096; idx += NBLK * NTHR) {
        int ct = idx / 32768, rem = idx - ct * 32768;
        int ch = rem >> 12, rr = rem & 4095;
        int k = rr >> 6, n = rr & 63;
        int np = ct * 64 + n, kk = ch * 64 + k;
        float w = Wconcat[np * 512 + kk];
        bf16 hi = __float2bfloat16(w);
        bf16 lo = __float2bfloat16(w - __bfloat162float(hi));
        unsigned char* base = g_Wccw + (size_t)(ct * 8 + ch) * 16384;
        uint32_t off = SWZ((uint32_t)(k * 128 + n * 2));
        *(bf16*)(base + off) = hi;
        *(bf16*)(base + 8192 + off) = lo;
    }
    {
        int g = bid * NTHR + tid;   // exactly 65536 threads
        int i = g >> 8, j = g & 255;
        float acc = 0.f;
        const float* wc = Wcrit + i * 256;
#pragma unroll 4
        for (int k = 0; k < 256; k++) acc += wc[k] * Wout[k * 256 + j];
        g_Wco[i * 256 + j] = acc;
    }
    for (int idx = bid * NTHR + tid; idx < 1024; idx += NBLK * NTHR) {
        int h = idx >> 2, g = idx & 3, orow = g * 256 + h;
        g_b0p[idx] = bih0[orow] + bhh0[orow];
        g_b1p[idx] = bih1[orow] + bhh1[orow];
    }
    for (int idx = bid * NTHR + tid; idx < 65536; idx += NBLK * NTHR)
        split1(emb[idx], g_embh + idx, g_embl + idx);
    for (int idx = bid * NTHR + tid; idx < Bq * 256; idx += NBLK * NTHR) {
        split1(enc_h[idx], g_h0ah + idx, g_h0al + idx);
        split1(enc_h[Bq * 256 + idx], g_h1ah + idx, g_h1al + idx);
        g_c0[idx] = enc_c[idx];
        g_c1[idx] = enc_c[Bq * 256 + idx];
        int b = idx >> 8, hh = idx & 255;
        const float* p = enc_out + (size_t)b * Lq * 256 + hh;
        float s = 0.f;
        for (int l = 0; l < Lq; l++) s += p[(size_t)l * 256];
        split1(s * (1.0f / Lq), g_ctxh + idx, g_ctxl + idx);
    }
    bt += NBLK; gsync(bt);
    for (int idx = bid * NTHR + tid; idx < 8 * 4 * 4096; idx += NBLK * NTHR) {
        int ct = idx / 16384, rem = idx - ct * 16384;
        int ch = rem >> 12, rr = rem & 4095;
        int k = rr >> 6, n = rr & 63;
        int np = ct * 64 + n, kk = ch * 64 + k;
        float w = (np < 256) ? Wout[np * 256 + kk] : g_Wco[(np - 256) * 256 + kk];
        bf16 hi = __float2bfloat16(w);
        bf16 lo = __float2bfloat16(w - __bfloat162float(hi));
        unsigned char* base = g_Wskw + (size_t)(ct * 4 + ch) * 16384;
        uint32_t off = SWZ((uint32_t)(k * 128 + n * 2));
        *(bf16*)(base + off) = hi;
        *(bf16*)(base + 8192 + off) = lo;
    }
    bt += NBLK; gsync(bt);

    bf16 *h0ch = g_h0ah, *h0cl = g_h0al, *h0nh = g_h0bh, *h0nl = g_h0bl;
    bf16 *h1ch = g_h1ah, *h1cl = g_h1al, *h1nh = g_h1bh, *h1nl = g_h1bl;
    const int bmL = (bid >> 4) * 64, ctL = bid & 15;   // 16 bm x 16 ct = 256

    for (int t = 0; t < Lq; t++) {
        // P1: LSTM0 [emb(gather) | ctx | h0]
        if (tid < 64)
            gidx[tid] = (t == 0) ? 0 : actions[(bmL + tid) * Lq + (t - 1)];
        __syncthreads();
        lstm_mma(dynsm, smb, gidx, bmL, ctL,
                 g_embh, g_embl, g_ctxh, g_ctxl, h0ch, h0cl, 12, true,
                 g_W0sw + (size_t)ctL * (12 * 16384), g_b0p, g_c0, h0nh, h0nl);
        bt += NBLK; gsync(bt);
        // P2: LSTM1 [h0n | h1c]
        lstm_mma(dynsm, smb, gidx, bmL, ctL,
                 h0nh, h0nl, h1ch, h1cl, nullptr, nullptr, 8, false,
                 g_W1sw + (size_t)ctL * (8 * 16384), g_b1p, g_c1, h1nh, h1nl);
        bt += NBLK; gsync(bt);
        // P3: 0-63 q = h1@Wa (16bm x 4ct); 64-127 pre = h1@Wcc1
        if (bid < 64) {
            mma_out64(dynsm, smb, (bid >> 2) * 64, bid & 3, h1nh, h1nl, 4,
                      g_Waw + (size_t)(bid & 3) * (4 * 16384), nullptr, 0,
                      g_q, nullptr, nullptr, nullptr);
        } else if (bid < 128) {
            int b2 = bid - 64;
            mma_out64(dynsm, smb, (b2 >> 2) * 64, b2 & 3, h1nh, h1nl, 4,
                      g_Wccw + (size_t)(b2 & 3) * (8 * 16384), nullptr, 0,
                      g_pre, nullptr, nullptr, nullptr);
        }
        bt += NBLK; gsync(bt);
        // P4: attention (4 rows/block x 256 blocks = 1024)
        attention4(sp, bid, enc_out);
        bt += NBLK; gsync(bt);
        // P5: ctx = tanh(pre + ctx_att@Wcc2) (64 tiles)
        if (bid < 64)
            mma_out64(dynsm, smb, (bid >> 2) * 64, bid & 3, g_cah, g_cal, 4,
                      g_Wccw + (size_t)(bid & 3) * (8 * 16384) + 4 * 16384,
                      nullptr, 4, nullptr, g_pre, g_ctxh, g_ctxl);
        bt += NBLK; gsync(bt);
        // P6: [logit|Q] = ctx @ [Wout;Wco]^T + [0|bcrit] (16bm x 8ct = 128 tiles)
        if (bid < 128)
            mma_out64(dynsm, smb, (bid >> 3) * 64, bid & 7, g_ctxh, g_ctxl, 4,
                      g_Wskw + (size_t)(bid & 7) * (4 * 16384), bcrit, 3,
                      g_logit, g_Q, nullptr, nullptr);
        bt += NBLK; gsync(bt);
        // P7: finalize (4 rows/block, no trailing barrier)
        finalize4(bid, t, actions, out);
        bf16* tp;
        tp = h0ch; h0ch = h0nh; h0nh = tp;
        tp = h0cl; h0cl = h0nl; h0nl = tp;
        tp = h1ch; h1ch = h1nh; h1nh = tp;
        tp = h1cl; h1cl = h1nl; h1nl = tp;
    }
}

__global__ void reset_k() { g_count = 0; }

// ---------------- host ----------------
extern "C" void kernel_launch(void* const* d_in, const int* in_sizes, int n_in,
                              void* d_out, int out_size) {
    const float* enc_out = (const float*)d_in[0];
    const float* enc_h   = (const float*)d_in[1];
    const float* enc_c   = (const float*)d_in[2];
    const float* emb     = (const float*)d_in[3];
    const float* Wih0    = (const float*)d_in[4];
    const float* Whh0    = (const float*)d_in[5];
    const float* bih0    = (const float*)d_in[6];
    const float* bhh0    = (const float*)d_in[7];
    const float* Wih1    = (const float*)d_in[8];
    const float* Whh1    = (const float*)d_in[9];
    const float* bih1    = (const float*)d_in[10];
    const float* bhh1    = (const float*)d_in[11];
    const float* Wa      = (const float*)d_in[12];
    const float* Wconcat = (const float*)d_in[13];
    const float* Wout    = (const float*)d_in[14];
    const float* Wcrit   = (const float*)d_in[15];
    const float* bcrit   = (const float*)d_in[16];
    const int*   actions = (const int*)d_in[17];
    float* out = (float*)d_out;

    cudaFuncSetAttribute(mega, cudaFuncAttributeMaxDynamicSharedMemorySize, SMEM_TOTAL);
    reset_k<<<1, 1>>>();
    mega<<<NBLK, NTHR, SMEM_TOTAL>>>(enc_out, enc_h, enc_c, emb,
                                     Wih0, Whh0, bih0, bhh0,
                                     Wih1, Whh1, bih1, bhh1,
                                     Wa, Wconcat, Wout, Wcrit, bcrit, actions, out);
}